// round 1
// baseline (speedup 1.0000x reference)
#include <cuda_runtime.h>

// Problem constants
#define BB 4
#define TT 4096
#define CC 512
#define HH 64

#define BM 64     // queries per CTA
#define BN 32     // keys per tile
#define PROJ_ROWS 16

// Scratch for q, k, v projections (4 MB each)
__device__ float g_q[BB * TT * HH];
__device__ float g_k[BB * TT * HH];
__device__ float g_v[BB * TT * HH];

// ---------------------------------------------------------------------------
// Projection: [B*T, 512] @ [512, 64] for Wq, Wk, Wv simultaneously.
// 192 threads: thread = (mat, col). x tile (16 rows) staged in smem,
// broadcast-read; float4 x loads give 4 FFMA per LDS.128.
// ---------------------------------------------------------------------------
__global__ __launch_bounds__(192) void proj_kernel(
    const float* __restrict__ x,
    const float* __restrict__ Wq,
    const float* __restrict__ Wk,
    const float* __restrict__ Wv)
{
    __shared__ float4 xs[PROJ_ROWS * CC / 4];   // 16 * 128 float4 = 32 KB

    const int row0 = blockIdx.x * PROJ_ROWS;
    const float4* xg = reinterpret_cast<const float4*>(x + (size_t)row0 * CC);
    for (int i = threadIdx.x; i < PROJ_ROWS * CC / 4; i += 192) xs[i] = xg[i];
    __syncthreads();

    const int mat = threadIdx.x / 64;   // 0=q, 1=k, 2=v
    const int col = threadIdx.x % 64;
    const float* __restrict__ W = (mat == 0) ? Wq : ((mat == 1) ? Wk : Wv);
    float* __restrict__ out = (mat == 0) ? g_q : ((mat == 1) ? g_k : g_v);

    float acc[PROJ_ROWS];
#pragma unroll
    for (int r = 0; r < PROJ_ROWS; r++) acc[r] = 0.0f;

    for (int k0 = 0; k0 < CC; k0 += 4) {
        const float w0 = W[(k0 + 0) * HH + col];
        const float w1 = W[(k0 + 1) * HH + col];
        const float w2 = W[(k0 + 2) * HH + col];
        const float w3 = W[(k0 + 3) * HH + col];
#pragma unroll
        for (int r = 0; r < PROJ_ROWS; r++) {
            const float4 xv = xs[r * (CC / 4) + (k0 >> 2)];
            acc[r] += xv.x * w0;
            acc[r] += xv.y * w1;
            acc[r] += xv.z * w2;
            acc[r] += xv.w * w3;
        }
    }
#pragma unroll
    for (int r = 0; r < PROJ_ROWS; r++)
        out[(size_t)(row0 + r) * HH + col] = acc[r];
}

// ---------------------------------------------------------------------------
// Flash attention (causal, scale = 1/sqrt(512)).
// CTA = 64 queries of one batch. 256 threads: 4 threads per query,
// each owning 16 head dims. K tiled by 32 keys; K/V tiles in smem.
// Online softmax per tile; score vector (32) lives in registers.
// Heavy query-blocks launch first (qb = 63 - blockIdx.x) for balance.
// ---------------------------------------------------------------------------
__global__ __launch_bounds__(256) void attn_kernel(float* __restrict__ out)
{
    const int b  = blockIdx.y;
    const int qb = 63 - (int)blockIdx.x;        // heavy first
    const int tid  = threadIdx.x;
    const int g    = tid >> 2;                  // query within block [0,64)
    const int part = tid & 3;                   // dim quarter
    const int d0   = part * 16;

    __shared__ float ks[BN * HH];               // 8 KB
    __shared__ float vs[BN * HH];               // 8 KB

    const int   qi   = qb * BM + g;             // query index within batch
    const int   qrow = b * TT + qi;
    const float scale = 0.044194173824159216f;  // 512^-0.5

    // Load q (pre-scaled)
    float qr[16];
    {
        const float4* qp = reinterpret_cast<const float4*>(g_q + (size_t)qrow * HH + d0);
        const float4 a = qp[0], c = qp[1], e = qp[2], f = qp[3];
        qr[0]=a.x*scale; qr[1]=a.y*scale; qr[2]=a.z*scale; qr[3]=a.w*scale;
        qr[4]=c.x*scale; qr[5]=c.y*scale; qr[6]=c.z*scale; qr[7]=c.w*scale;
        qr[8]=e.x*scale; qr[9]=e.y*scale; qr[10]=e.z*scale; qr[11]=e.w*scale;
        qr[12]=f.x*scale; qr[13]=f.y*scale; qr[14]=f.z*scale; qr[15]=f.w*scale;
    }

    const float NEG = -3.0e38f;
    float m = NEG, l = 0.0f;
    float acc[16];
#pragma unroll
    for (int i = 0; i < 16; i++) acc[i] = 0.0f;

    const int ntiles = 2 * qb + 2;              // key tiles of 32
    for (int kt = 0; kt < ntiles; kt++) {
        __syncthreads();
        // Cooperative tile load (512 float4 per tile, 2 per thread each)
        {
            const float4* kg = reinterpret_cast<const float4*>(g_k + (size_t)(b * TT + kt * BN) * HH);
            const float4* vg = reinterpret_cast<const float4*>(g_v + (size_t)(b * TT + kt * BN) * HH);
            float4* ks4 = reinterpret_cast<float4*>(ks);
            float4* vs4 = reinterpret_cast<float4*>(vs);
            ks4[tid]       = kg[tid];
            ks4[256 + tid] = kg[256 + tid];
            vs4[tid]       = vg[tid];
            vs4[256 + tid] = vg[256 + tid];
        }
        __syncthreads();

        // Scores for 32 keys
        float s[BN];
#pragma unroll
        for (int j = 0; j < BN; j++) {
            const float4* kr = reinterpret_cast<const float4*>(ks + j * HH + d0);
            const float4 a = kr[0], c = kr[1], e = kr[2], f = kr[3];
            float sv = qr[0]*a.x + qr[1]*a.y + qr[2]*a.z + qr[3]*a.w
                     + qr[4]*c.x + qr[5]*c.y + qr[6]*c.z + qr[7]*c.w
                     + qr[8]*e.x + qr[9]*e.y + qr[10]*e.z + qr[11]*e.w
                     + qr[12]*f.x + qr[13]*f.y + qr[14]*f.z + qr[15]*f.w;
            sv += __shfl_xor_sync(0xffffffffu, sv, 1);
            sv += __shfl_xor_sync(0xffffffffu, sv, 2);
            s[j] = sv;
        }

        // Causal mask (only last two tiles can be partial)
        const int lim = qi - kt * BN;           // keys j <= lim are valid
        if (lim < BN - 1) {
#pragma unroll
            for (int j = 0; j < BN; j++)
                if (j > lim) s[j] = NEG;
        }

        // Online softmax update
        float mt = m;
#pragma unroll
        for (int j = 0; j < BN; j++) mt = fmaxf(mt, s[j]);
        const float alpha = __expf(m - mt);
        m = mt;
        l *= alpha;
#pragma unroll
        for (int i = 0; i < 16; i++) acc[i] *= alpha;

#pragma unroll
        for (int j = 0; j < BN; j++) {
            const float p = __expf(s[j] - mt);
            l += p;
            const float4* vr = reinterpret_cast<const float4*>(vs + j * HH + d0);
            const float4 a = vr[0], c = vr[1], e = vr[2], f = vr[3];
            acc[0]  += p * a.x;  acc[1]  += p * a.y;  acc[2]  += p * a.z;  acc[3]  += p * a.w;
            acc[4]  += p * c.x;  acc[5]  += p * c.y;  acc[6]  += p * c.z;  acc[7]  += p * c.w;
            acc[8]  += p * e.x;  acc[9]  += p * e.y;  acc[10] += p * e.z;  acc[11] += p * e.w;
            acc[12] += p * f.x;  acc[13] += p * f.y;  acc[14] += p * f.z;  acc[15] += p * f.w;
        }
    }

    const float inv = 1.0f / l;
    float* op = out + (size_t)qrow * HH + d0;
    float4* op4 = reinterpret_cast<float4*>(op);
    float4 o;
    o.x = acc[0]*inv;  o.y = acc[1]*inv;  o.z = acc[2]*inv;  o.w = acc[3]*inv;  op4[0] = o;
    o.x = acc[4]*inv;  o.y = acc[5]*inv;  o.z = acc[6]*inv;  o.w = acc[7]*inv;  op4[1] = o;
    o.x = acc[8]*inv;  o.y = acc[9]*inv;  o.z = acc[10]*inv; o.w = acc[11]*inv; op4[2] = o;
    o.x = acc[12]*inv; o.y = acc[13]*inv; o.z = acc[14]*inv; o.w = acc[15]*inv; op4[3] = o;
}

// ---------------------------------------------------------------------------
extern "C" void kernel_launch(void* const* d_in, const int* in_sizes, int n_in,
                              void* d_out, int out_size)
{
    const float* x  = (const float*)d_in[0];
    const float* Wq = (const float*)d_in[1];
    const float* Wk = (const float*)d_in[2];
    const float* Wv = (const float*)d_in[3];
    float* out = (float*)d_out;

    proj_kernel<<<BB * TT / PROJ_ROWS, 192>>>(x, Wq, Wk, Wv);
    attn_kernel<<<dim3(TT / BM, BB), 256>>>(out);
}

// round 2
// speedup vs baseline: 6.6127x; 6.6127x over previous
#include <cuda_runtime.h>

// Problem constants
#define BB 4
#define TT 4096
#define CC 512
#define HH 64

#define BM 64      // queries per CTA
#define BN 64      // keys per tile
#define PROJ_ROWS 16

#define KSTRIDE 68 // smem stride (floats) for K tile / P tile
#define VSTRIDE 72 // smem stride (floats) for V tile

// Scratch for q, k, v projections (4 MB each)
__device__ float g_q[BB * TT * HH];
__device__ float g_k[BB * TT * HH];
__device__ float g_v[BB * TT * HH];

// ---------------------------------------------------------------------------
// Projection: [B*T, 512] @ [512, 64] for Wq, Wk, Wv simultaneously (fp32).
// ---------------------------------------------------------------------------
__global__ __launch_bounds__(192) void proj_kernel(
    const float* __restrict__ x,
    const float* __restrict__ Wq,
    const float* __restrict__ Wk,
    const float* __restrict__ Wv)
{
    __shared__ float4 xs[PROJ_ROWS * CC / 4];   // 32 KB

    const int row0 = blockIdx.x * PROJ_ROWS;
    const float4* xg = reinterpret_cast<const float4*>(x + (size_t)row0 * CC);
    for (int i = threadIdx.x; i < PROJ_ROWS * CC / 4; i += 192) xs[i] = xg[i];
    __syncthreads();

    const int mat = threadIdx.x / 64;
    const int col = threadIdx.x % 64;
    const float* __restrict__ W = (mat == 0) ? Wq : ((mat == 1) ? Wk : Wv);
    float* __restrict__ out = (mat == 0) ? g_q : ((mat == 1) ? g_k : g_v);

    float acc[PROJ_ROWS];
#pragma unroll
    for (int r = 0; r < PROJ_ROWS; r++) acc[r] = 0.0f;

    for (int k0 = 0; k0 < CC; k0 += 4) {
        const float w0 = W[(k0 + 0) * HH + col];
        const float w1 = W[(k0 + 1) * HH + col];
        const float w2 = W[(k0 + 2) * HH + col];
        const float w3 = W[(k0 + 3) * HH + col];
#pragma unroll
        for (int r = 0; r < PROJ_ROWS; r++) {
            const float4 xv = xs[r * (CC / 4) + (k0 >> 2)];
            acc[r] += xv.x * w0;
            acc[r] += xv.y * w1;
            acc[r] += xv.z * w2;
            acc[r] += xv.w * w3;
        }
    }
#pragma unroll
    for (int r = 0; r < PROJ_ROWS; r++)
        out[(size_t)(row0 + r) * HH + col] = acc[r];
}

// ---------------------------------------------------------------------------
// tf32 helpers
// ---------------------------------------------------------------------------
__device__ __forceinline__ unsigned f2tf(float f) {
    unsigned u;
    asm("cvt.rna.tf32.f32 %0, %1;" : "=r"(u) : "f"(f));
    return u;
}

__device__ __forceinline__ void mma_tf32(
    float& c0, float& c1, float& c2, float& c3,
    unsigned a0, unsigned a1, unsigned a2, unsigned a3,
    unsigned b0, unsigned b1)
{
    asm("mma.sync.aligned.m16n8k8.row.col.f32.tf32.tf32.f32 "
        "{%0,%1,%2,%3}, {%4,%5,%6,%7}, {%8,%9}, {%0,%1,%2,%3};"
        : "+f"(c0), "+f"(c1), "+f"(c2), "+f"(c3)
        : "r"(a0), "r"(a1), "r"(a2), "r"(a3), "r"(b0), "r"(b1));
}

// ---------------------------------------------------------------------------
// Flash attention, tf32 tensor-core version.
// CTA: 128 threads = 4 warps; warp w owns query rows [w*16, w*16+16).
// S = Q K^T via m16n8k8 (A = Q row-major frags in regs, B = K rows from smem).
// Online softmax in C-fragment registers; P staged per-warp in smem (aliases
// the K tile), then O += P V via a second mma sweep.
// ---------------------------------------------------------------------------
__global__ __launch_bounds__(128) void attn_kernel(float* __restrict__ out)
{
    const int b  = blockIdx.y;
    const int qb = 63 - (int)blockIdx.x;      // heavy blocks first
    const int tid = threadIdx.x;
    const int w   = tid >> 5;                 // warp 0..3
    const int lane = tid & 31;
    const int g = lane >> 2;                  // 0..7
    const int t = lane & 3;                   // 0..3

    // K tile (tf32 bits), aliased by P after S-phase. V tile (tf32 bits).
    __shared__ unsigned sm_k[BN * KSTRIDE];   // 17408 B
    __shared__ unsigned sm_v[BN * VSTRIDE];   // 18432 B
    unsigned* ps = sm_k;                      // P alias: warp-private 16 rows

    const float scale = 0.044194173824159216f;  // 512^-0.5

    const int qrow0 = qb * BM + w * 16 + g;      // query row (batch-local), row g
    const int grow0 = b * TT + qrow0;            // global row for rows g
    const int grow1 = grow0 + 8;                 // rows g+8

    // Q as tf32 A-fragments, pre-scaled. 8 k-steps x 4 regs.
    unsigned qa[8][4];
#pragma unroll
    for (int kk = 0; kk < 8; kk++) {
        const int c0 = 8 * kk + t;
        qa[kk][0] = f2tf(scale * g_q[(size_t)grow0 * HH + c0]);
        qa[kk][1] = f2tf(scale * g_q[(size_t)grow1 * HH + c0]);
        qa[kk][2] = f2tf(scale * g_q[(size_t)grow0 * HH + c0 + 4]);
        qa[kk][3] = f2tf(scale * g_q[(size_t)grow1 * HH + c0 + 4]);
    }

    float oacc[8][4];
#pragma unroll
    for (int j = 0; j < 8; j++)
#pragma unroll
        for (int i = 0; i < 4; i++) oacc[j][i] = 0.0f;

    const float NEG = -3.0e38f;
    float m0 = NEG, m1 = NEG, l0 = 0.0f, l1 = 0.0f;

    const int ntiles = qb + 1;
    for (int kt = 0; kt < ntiles; kt++) {
        __syncthreads();   // previous tile fully consumed (K/P and V)

        // --- Fill K and V tiles (convert to tf32 bits at store) ---
        {
            const int kvbase = (b * TT + kt * BN);
            for (int i = tid; i < BN * 16; i += 128) {
                const int r  = i >> 4;
                const int c4 = (i & 15) * 4;
                const float4 kv = *reinterpret_cast<const float4*>(
                    g_k + (size_t)(kvbase + r) * HH + c4);
                const float4 vv = *reinterpret_cast<const float4*>(
                    g_v + (size_t)(kvbase + r) * HH + c4);
                unsigned* kd = &sm_k[r * KSTRIDE + c4];
                kd[0] = f2tf(kv.x); kd[1] = f2tf(kv.y);
                kd[2] = f2tf(kv.z); kd[3] = f2tf(kv.w);
                unsigned* vd = &sm_v[r * VSTRIDE + c4];
                vd[0] = f2tf(vv.x); vd[1] = f2tf(vv.y);
                vd[2] = f2tf(vv.z); vd[3] = f2tf(vv.w);
            }
        }
        __syncthreads();

        // --- S = Q K^T  (64 x 64 per CTA; 16 x 64 per warp) ---
        float s[8][4];
#pragma unroll
        for (int j = 0; j < 8; j++) {
            float c0 = 0.f, c1 = 0.f, c2 = 0.f, c3 = 0.f;
            const unsigned* krow = &sm_k[(8 * j + g) * KSTRIDE];
#pragma unroll
            for (int kk = 0; kk < 8; kk++) {
                const unsigned b0 = krow[8 * kk + t];
                const unsigned b1 = krow[8 * kk + t + 4];
                mma_tf32(c0, c1, c2, c3,
                         qa[kk][0], qa[kk][1], qa[kk][2], qa[kk][3], b0, b1);
            }
            s[j][0] = c0; s[j][1] = c1; s[j][2] = c2; s[j][3] = c3;
        }

        __syncthreads();   // all warps done reading K before P overwrites it

        // --- Causal mask (only the diagonal tile needs it) ---
        if (kt == qb) {
            const int colbase = kt * BN + 2 * t;
            const int r0 = qrow0;        // batch-local row g
            const int r1 = qrow0 + 8;    // row g+8
#pragma unroll
            for (int j = 0; j < 8; j++) {
                const int c = colbase + 8 * j;
                if (c     > r0) s[j][0] = NEG;
                if (c + 1 > r0) s[j][1] = NEG;
                if (c     > r1) s[j][2] = NEG;
                if (c + 1 > r1) s[j][3] = NEG;
            }
        }

        // --- Online softmax ---
        float tm0 = NEG, tm1 = NEG;
#pragma unroll
        for (int j = 0; j < 8; j++) {
            tm0 = fmaxf(tm0, fmaxf(s[j][0], s[j][1]));
            tm1 = fmaxf(tm1, fmaxf(s[j][2], s[j][3]));
        }
        tm0 = fmaxf(tm0, __shfl_xor_sync(0xffffffffu, tm0, 1));
        tm0 = fmaxf(tm0, __shfl_xor_sync(0xffffffffu, tm0, 2));
        tm1 = fmaxf(tm1, __shfl_xor_sync(0xffffffffu, tm1, 1));
        tm1 = fmaxf(tm1, __shfl_xor_sync(0xffffffffu, tm1, 2));

        const float mt0 = fmaxf(m0, tm0);
        const float mt1 = fmaxf(m1, tm1);
        const float alpha0 = __expf(m0 - mt0);
        const float alpha1 = __expf(m1 - mt1);
        m0 = mt0; m1 = mt1;

#pragma unroll
        for (int j = 0; j < 8; j++) {
            oacc[j][0] *= alpha0; oacc[j][1] *= alpha0;
            oacc[j][2] *= alpha1; oacc[j][3] *= alpha1;
        }

        float rs0 = 0.0f, rs1 = 0.0f;
        unsigned* pw = &ps[(w * 16) * KSTRIDE];
#pragma unroll
        for (int j = 0; j < 8; j++) {
            const float p0 = __expf(s[j][0] - mt0);
            const float p1 = __expf(s[j][1] - mt0);
            const float p2 = __expf(s[j][2] - mt1);
            const float p3 = __expf(s[j][3] - mt1);
            rs0 += p0 + p1;
            rs1 += p2 + p3;
            // Store P as tf32 bits: rows g and g+8, cols 8j+2t, 8j+2t+1
            uint2 u01; u01.x = f2tf(p0); u01.y = f2tf(p1);
            uint2 u23; u23.x = f2tf(p2); u23.y = f2tf(p3);
            *reinterpret_cast<uint2*>(&pw[g * KSTRIDE + 8 * j + 2 * t]) = u01;
            *reinterpret_cast<uint2*>(&pw[(g + 8) * KSTRIDE + 8 * j + 2 * t]) = u23;
        }
        rs0 += __shfl_xor_sync(0xffffffffu, rs0, 1);
        rs0 += __shfl_xor_sync(0xffffffffu, rs0, 2);
        rs1 += __shfl_xor_sync(0xffffffffu, rs1, 1);
        rs1 += __shfl_xor_sync(0xffffffffu, rs1, 2);
        l0 = l0 * alpha0 + rs0;
        l1 = l1 * alpha1 + rs1;

        __syncwarp();      // P visible within warp

        // --- O += P V  (A = P from smem, B = V from smem) ---
        unsigned pa[8][4];
#pragma unroll
        for (int kk = 0; kk < 8; kk++) {
            const int c0 = 8 * kk + t;
            pa[kk][0] = pw[g * KSTRIDE + c0];
            pa[kk][1] = pw[(g + 8) * KSTRIDE + c0];
            pa[kk][2] = pw[g * KSTRIDE + c0 + 4];
            pa[kk][3] = pw[(g + 8) * KSTRIDE + c0 + 4];
        }
#pragma unroll
        for (int j = 0; j < 8; j++) {
#pragma unroll
            for (int kk = 0; kk < 8; kk++) {
                const unsigned b0 = sm_v[(8 * kk + t) * VSTRIDE + 8 * j + g];
                const unsigned b1 = sm_v[(8 * kk + t + 4) * VSTRIDE + 8 * j + g];
                mma_tf32(oacc[j][0], oacc[j][1], oacc[j][2], oacc[j][3],
                         pa[kk][0], pa[kk][1], pa[kk][2], pa[kk][3], b0, b1);
            }
        }
    }

    // --- Epilogue: normalize and store ---
    const float inv0 = 1.0f / l0;
    const float inv1 = 1.0f / l1;
#pragma unroll
    for (int j = 0; j < 8; j++) {
        const int c = 8 * j + 2 * t;
        float2 o0; o0.x = oacc[j][0] * inv0; o0.y = oacc[j][1] * inv0;
        float2 o1; o1.x = oacc[j][2] * inv1; o1.y = oacc[j][3] * inv1;
        *reinterpret_cast<float2*>(out + (size_t)grow0 * HH + c) = o0;
        *reinterpret_cast<float2*>(out + (size_t)grow1 * HH + c) = o1;
    }
}

// ---------------------------------------------------------------------------
extern "C" void kernel_launch(void* const* d_in, const int* in_sizes, int n_in,
                              void* d_out, int out_size)
{
    const float* x  = (const float*)d_in[0];
    const float* Wq = (const float*)d_in[1];
    const float* Wk = (const float*)d_in[2];
    const float* Wv = (const float*)d_in[3];
    float* out = (float*)d_out;

    proj_kernel<<<BB * TT / PROJ_ROWS, 192>>>(x, Wq, Wk, Wv);
    attn_kernel<<<dim3(TT / BM, BB), 128>>>(out);
}